// round 6
// baseline (speedup 1.0000x reference)
#include <cuda_runtime.h>
#include <math.h>

#define EMBED 1024
#define QKVN  1536
#define INNER 512
#define NHEAD 8
#define HDIM  64
#define BATCH 2
#define SEQ   4096
#define MROWS (BATCH * SEQ)   // 8192

// Scratch (allocation-free rule: __device__ globals)
__device__ float g_q[BATCH * NHEAD * SEQ * HDIM];   // [B,H,N,D], pre-scaled by 0.125
__device__ float g_k[BATCH * NHEAD * SEQ * HDIM];
__device__ float g_v[BATCH * NHEAD * SEQ * HDIM];
__device__ float g_ao[MROWS * INNER];               // attention out, [B,N,H*D]

// ---------------------------------------------------------------------------
// TF32 mma helpers
// ---------------------------------------------------------------------------
__device__ __forceinline__ unsigned f2tf(float f) {
    unsigned u;
    asm("cvt.rna.tf32.f32 %0, %1;" : "=r"(u) : "f"(f));
    return u;
}

__device__ __forceinline__ void mma8(float* c, const unsigned* a, const unsigned* b) {
    asm volatile(
        "mma.sync.aligned.m16n8k8.row.col.f32.tf32.tf32.f32 "
        "{%0,%1,%2,%3}, {%4,%5,%6,%7}, {%8,%9}, {%0,%1,%2,%3};"
        : "+f"(c[0]), "+f"(c[1]), "+f"(c[2]), "+f"(c[3])
        : "r"(a[0]), "r"(a[1]), "r"(a[2]), "r"(a[3]), "r"(b[0]), "r"(b[1]));
}

// ---------------------------------------------------------------------------
// Shared GEMM mainloop: C[128x128] tile, BK=32, 256 threads (8 warps 2x4),
// warp tile 64x32 (4 m16 x 4 n8). tf32-rounded at smem store.
// As: [128][AST] m-major (AST=36, ≡4 mod 32 -> a-frag conflict-free)
// Bs: [32][BST]  k-major (BST=136, ≡8 mod 32 -> b-frag conflict-free)
// ---------------------------------------------------------------------------
#define AST 36
#define BST 136

template<int KDIM>
__device__ __forceinline__ void gemm_mainloop(
    const float* __restrict__ A, int lda,
    const float* __restrict__ B, int ldb,
    float acc[4][4][4], float* As, float* Bs, int row0, int col0)
{
    const int tid  = threadIdx.x;
    const int lane = tid & 31;
    const int warp = tid >> 5;
    const int wm   = (warp >> 2) * 64;
    const int wn   = (warp & 3) * 32;
    const int g    = lane >> 2, t = lane & 3;

    for (int kt = 0; kt < KDIM; kt += 32) {
        #pragma unroll
        for (int i = 0; i < 4; i++) {           // A tile 128x32
            int f = tid + i * 256;
            int r = f >> 3, c = (f & 7) * 4;
            float4 v = *(const float4*)&A[(size_t)(row0 + r) * lda + kt + c];
            unsigned* dst = (unsigned*)&As[r * AST + c];
            dst[0] = f2tf(v.x); dst[1] = f2tf(v.y);
            dst[2] = f2tf(v.z); dst[3] = f2tf(v.w);
        }
        #pragma unroll
        for (int i = 0; i < 4; i++) {           // B tile 32x128
            int f = tid + i * 256;
            int r = f >> 5, c = (f & 31) * 4;
            float4 v = *(const float4*)&B[(size_t)(kt + r) * ldb + col0 + c];
            unsigned* dst = (unsigned*)&Bs[r * BST + c];
            dst[0] = f2tf(v.x); dst[1] = f2tf(v.y);
            dst[2] = f2tf(v.z); dst[3] = f2tf(v.w);
        }
        __syncthreads();

        const unsigned* Au = (const unsigned*)As;
        const unsigned* Bu = (const unsigned*)Bs;
        #pragma unroll
        for (int ks = 0; ks < 4; ks++) {
            unsigned a[4][4], b[4][2];
            #pragma unroll
            for (int mt = 0; mt < 4; mt++) {
                int m = wm + mt * 16;
                a[mt][0] = Au[(m + g) * AST + ks * 8 + t];
                a[mt][1] = Au[(m + g + 8) * AST + ks * 8 + t];
                a[mt][2] = Au[(m + g) * AST + ks * 8 + t + 4];
                a[mt][3] = Au[(m + g + 8) * AST + ks * 8 + t + 4];
            }
            #pragma unroll
            for (int nt = 0; nt < 4; nt++) {
                int n = wn + nt * 8 + g;
                b[nt][0] = Bu[(ks * 8 + t) * BST + n];
                b[nt][1] = Bu[(ks * 8 + t + 4) * BST + n];
            }
            #pragma unroll
            for (int mt = 0; mt < 4; mt++)
                #pragma unroll
                for (int nt = 0; nt < 4; nt++)
                    mma8(acc[mt][nt], a[mt], b[nt]);
        }
        __syncthreads();
    }
}

// ---------------------------------------------------------------------------
// Kernel 1: QKV projection, scatter to Q/K/V [B,H,N,D]; Q pre-scaled.
// ---------------------------------------------------------------------------
__global__ __launch_bounds__(256) void qkv_gemm_kernel(
    const float* __restrict__ A,     // [8192, 1024]
    const float* __restrict__ W,     // [1024, 1536]
    const float* __restrict__ bias)  // [1536]
{
    __shared__ float As[128 * AST];
    __shared__ float Bs[32 * BST];
    const int tid  = threadIdx.x;
    const int lane = tid & 31, warp = tid >> 5;
    const int wm = (warp >> 2) * 64, wn = (warp & 3) * 32;
    const int g = lane >> 2, t = lane & 3;
    const int row0 = blockIdx.y * 128;
    const int col0 = blockIdx.x * 128;

    float acc[4][4][4];
    #pragma unroll
    for (int mt = 0; mt < 4; mt++)
        #pragma unroll
        for (int nt = 0; nt < 4; nt++)
            #pragma unroll
            for (int r = 0; r < 4; r++) acc[mt][nt][r] = 0.f;

    gemm_mainloop<EMBED>(A, EMBED, W, QKVN, acc, As, Bs, row0, col0);

    #pragma unroll
    for (int mt = 0; mt < 4; mt++) {
        #pragma unroll
        for (int half = 0; half < 2; half++) {
            int m  = row0 + wm + mt * 16 + g + half * 8;
            int bb = m >> 12;
            int n  = m & (SEQ - 1);
            #pragma unroll
            for (int nt = 0; nt < 4; nt++) {
                #pragma unroll
                for (int jj = 0; jj < 2; jj++) {
                    int o = col0 + wn + nt * 8 + t * 2 + jj;
                    float val = acc[mt][nt][half * 2 + jj] + bias[o];
                    int part  = o >> 9;
                    int inner = o & 511;
                    int h = inner >> 6, d = inner & 63;
                    size_t idx = (((size_t)(bb * NHEAD + h)) * SEQ + n) * HDIM + d;
                    if (part == 0)      g_q[idx] = val * 0.125f;
                    else if (part == 1) g_k[idx] = val;
                    else                g_v[idx] = val;
                }
            }
        }
    }
}

// ---------------------------------------------------------------------------
// Kernel 2: flash attention with tf32 mma. BQ=64, BKV=64, 128 threads.
// Warp w owns q rows [w*16, w*16+16). Fragments:
//   S = Q K^T : A from Qs (stride 68 ≡4), B from Ks (stride 68 ≡4 works: 4g+t)
//   O += P V  : A from Ps (stride 68),    B from Vs (stride 72 ≡8: 8t+g)
// ---------------------------------------------------------------------------
#define QST 68
#define KST 68
#define VST 72
#define PST 68
#define ATT_SMEM_BYTES ((64 * QST + 64 * KST + 64 * VST + 64 * PST) * 4)  // 70656

__global__ __launch_bounds__(128) void attn_kernel()
{
    extern __shared__ float sm[];
    float* Qs = sm;
    float* Ks = Qs + 64 * QST;
    float* Vs = Ks + 64 * KST;
    float* Ps = Vs + 64 * VST;

    const int tid  = threadIdx.x;
    const int lane = tid & 31, warp = tid >> 5;
    const int g = lane >> 2, t = lane & 3;
    const int bh = blockIdx.y;
    const int q0 = blockIdx.x * 64;
    const int w16 = warp * 16;

    const float* Qg = g_q + ((size_t)bh * SEQ + q0) * HDIM;
    const float* Kg = g_k + (size_t)bh * SEQ * HDIM;
    const float* Vg = g_v + (size_t)bh * SEQ * HDIM;

    // Load + round Q (64x64)
    #pragma unroll
    for (int i = 0; i < 8; i++) {
        int f = tid + i * 128;
        int r = f >> 4, c = (f & 15) * 4;
        float4 v = *(const float4*)&Qg[(size_t)r * HDIM + c];
        unsigned* dst = (unsigned*)&Qs[r * QST + c];
        dst[0] = f2tf(v.x); dst[1] = f2tf(v.y);
        dst[2] = f2tf(v.z); dst[3] = f2tf(v.w);
    }

    float o[8][4];
    float m_i[2], l_i[2];
    #pragma unroll
    for (int nt = 0; nt < 8; nt++)
        #pragma unroll
        for (int r = 0; r < 4; r++) o[nt][r] = 0.f;
    m_i[0] = m_i[1] = -1e30f;
    l_i[0] = l_i[1] = 0.f;

    const unsigned* Qu = (const unsigned*)Qs;
    const unsigned* Ku = (const unsigned*)Ks;
    const unsigned* Vu = (const unsigned*)Vs;
    const unsigned* Pu = (const unsigned*)Ps;

    for (int kt = 0; kt < SEQ; kt += 64) {
        __syncthreads();   // prior tile fully consumed (also orders Q on iter 0)
        #pragma unroll
        for (int i = 0; i < 8; i++) {
            int f = tid + i * 128;
            int r = f >> 4, c = (f & 15) * 4;
            float4 kv = *(const float4*)&Kg[(size_t)(kt + r) * HDIM + c];
            unsigned* kd = (unsigned*)&Ks[r * KST + c];
            kd[0] = f2tf(kv.x); kd[1] = f2tf(kv.y);
            kd[2] = f2tf(kv.z); kd[3] = f2tf(kv.w);
            float4 vv = *(const float4*)&Vg[(size_t)(kt + r) * HDIM + c];
            unsigned* vd = (unsigned*)&Vs[r * VST + c];
            vd[0] = f2tf(vv.x); vd[1] = f2tf(vv.y);
            vd[2] = f2tf(vv.z); vd[3] = f2tf(vv.w);
        }
        __syncthreads();

        // ---- S = Q K^T : 16 x 64 per warp ----
        float s[8][4];
        #pragma unroll
        for (int nt = 0; nt < 8; nt++)
            #pragma unroll
            for (int r = 0; r < 4; r++) s[nt][r] = 0.f;

        #pragma unroll
        for (int ks = 0; ks < 8; ks++) {
            unsigned a[4];
            a[0] = Qu[(w16 + g) * QST + ks * 8 + t];
            a[1] = Qu[(w16 + g + 8) * QST + ks * 8 + t];
            a[2] = Qu[(w16 + g) * QST + ks * 8 + t + 4];
            a[3] = Qu[(w16 + g + 8) * QST + ks * 8 + t + 4];
            #pragma unroll
            for (int nt = 0; nt < 8; nt++) {
                unsigned b[2];
                b[0] = Ku[(nt * 8 + g) * KST + ks * 8 + t];
                b[1] = Ku[(nt * 8 + g) * KST + ks * 8 + t + 4];
                mma8(s[nt], a, b);
            }
        }

        // ---- online softmax on C-fragment layout ----
        __syncwarp();      // prior PV reads of Ps done before overwrite
        #pragma unroll
        for (int half = 0; half < 2; half++) {
            float mx = -1e30f;
            #pragma unroll
            for (int nt = 0; nt < 8; nt++)
                mx = fmaxf(mx, fmaxf(s[nt][half * 2], s[nt][half * 2 + 1]));
            mx = fmaxf(mx, __shfl_xor_sync(0xffffffffu, mx, 1));
            mx = fmaxf(mx, __shfl_xor_sync(0xffffffffu, mx, 2));
            float mn   = fmaxf(m_i[half], mx);
            float corr = __expf(m_i[half] - mn);
            m_i[half] = mn;
            float sum = 0.f;
            #pragma unroll
            for (int nt = 0; nt < 8; nt++) {
                float p0 = __expf(s[nt][half * 2]     - mn);
                float p1 = __expf(s[nt][half * 2 + 1] - mn);
                sum += p0 + p1;
                unsigned* pd = (unsigned*)&Ps[(w16 + g + half * 8) * PST + nt * 8 + t * 2];
                pd[0] = f2tf(p0); pd[1] = f2tf(p1);
                o[nt][half * 2]     *= corr;
                o[nt][half * 2 + 1] *= corr;
            }
            sum += __shfl_xor_sync(0xffffffffu, sum, 1);
            sum += __shfl_xor_sync(0xffffffffu, sum, 2);
            l_i[half] = l_i[half] * corr + sum;
        }
        __syncwarp();      // P visible to whole warp before PV loads

        // ---- O += P V ----
        #pragma unroll
        for (int ks = 0; ks < 8; ks++) {
            unsigned a[4];
            a[0] = Pu[(w16 + g) * PST + ks * 8 + t];
            a[1] = Pu[(w16 + g + 8) * PST + ks * 8 + t];
            a[2] = Pu[(w16 + g) * PST + ks * 8 + t + 4];
            a[3] = Pu[(w16 + g + 8) * PST + ks * 8 + t + 4];
            #pragma unroll
            for (int nt = 0; nt < 8; nt++) {
                unsigned b[2];
                b[0] = Vu[(ks * 8 + t) * VST + nt * 8 + g];
                b[1] = Vu[(ks * 8 + t + 4) * VST + nt * 8 + g];
                mma8(o[nt], a, b);
            }
        }
    }

    // finalize + write [B,N,H*D]
    const int bb = bh >> 3, h = bh & 7;
    #pragma unroll
    for (int half = 0; half < 2; half++) {
        float inv = 1.0f / l_i[half];
        int n = q0 + w16 + g + half * 8;
        float* dst = g_ao + ((size_t)(bb * SEQ + n)) * INNER + h * HDIM;
        #pragma unroll
        for (int nt = 0; nt < 8; nt++) {
            float2 v2;
            v2.x = o[nt][half * 2]     * inv;
            v2.y = o[nt][half * 2 + 1] * inv;
            *(float2*)&dst[nt * 8 + t * 2] = v2;
        }
    }
}

// ---------------------------------------------------------------------------
// Kernel 3: output projection  out = AO @ Wproj + b
// ---------------------------------------------------------------------------
__global__ __launch_bounds__(256) void proj_gemm_kernel(
    const float* __restrict__ W,     // [512, 1024]
    const float* __restrict__ bias,  // [1024]
    float* __restrict__ out)         // [8192, 1024]
{
    __shared__ float As[128 * AST];
    __shared__ float Bs[32 * BST];
    const int tid  = threadIdx.x;
    const int lane = tid & 31, warp = tid >> 5;
    const int wm = (warp >> 2) * 64, wn = (warp & 3) * 32;
    const int g = lane >> 2, t = lane & 3;
    const int row0 = blockIdx.y * 128;
    const int col0 = blockIdx.x * 128;

    float acc[4][4][4];
    #pragma unroll
    for (int mt = 0; mt < 4; mt++)
        #pragma unroll
        for (int nt = 0; nt < 4; nt++)
            #pragma unroll
            for (int r = 0; r < 4; r++) acc[mt][nt][r] = 0.f;

    gemm_mainloop<INNER>(g_ao, INNER, W, EMBED, acc, As, Bs, row0, col0);

    #pragma unroll
    for (int mt = 0; mt < 4; mt++) {
        #pragma unroll
        for (int half = 0; half < 2; half++) {
            int m = row0 + wm + mt * 16 + g + half * 8;
            #pragma unroll
            for (int nt = 0; nt < 4; nt++) {
                int n = col0 + wn + nt * 8 + t * 2;
                float2 v2;
                v2.x = acc[mt][nt][half * 2]     + bias[n];
                v2.y = acc[mt][nt][half * 2 + 1] + bias[n + 1];
                *(float2*)&out[(size_t)m * EMBED + n] = v2;
            }
        }
    }
}

// ---------------------------------------------------------------------------
extern "C" void kernel_launch(void* const* d_in, const int* in_sizes, int n_in,
                              void* d_out, int out_size)
{
    const float* X     = (const float*)d_in[0];
    const float* Wqkv  = (const float*)d_in[1];
    const float* Bqkv  = (const float*)d_in[2];
    const float* Wproj = (const float*)d_in[3];
    const float* Bproj = (const float*)d_in[4];
    float* out = (float*)d_out;

    cudaFuncSetAttribute(attn_kernel,
                         cudaFuncAttributeMaxDynamicSharedMemorySize,
                         ATT_SMEM_BYTES);

    qkv_gemm_kernel<<<dim3(QKVN / 128, MROWS / 128), 256>>>(X, Wqkv, Bqkv);
    attn_kernel<<<dim3(SEQ / 64, BATCH * NHEAD), 128, ATT_SMEM_BYTES>>>();
    proj_gemm_kernel<<<dim3(EMBED / 128, MROWS / 128), 256>>>(Wproj, Bproj, out);
}

// round 7
// speedup vs baseline: 1.0004x; 1.0004x over previous
#include <cuda_runtime.h>
#include <math.h>

#define EMBED 1024
#define QKVN  1536
#define INNER 512
#define NHEAD 8
#define HDIM  64
#define BATCH 2
#define SEQ   4096
#define MROWS (BATCH * SEQ)   // 8192

// Scratch (allocation-free rule: __device__ globals)
__device__ float g_q[BATCH * NHEAD * SEQ * HDIM];   // [B,H,N,D], pre-scaled by 0.125
__device__ float g_k[BATCH * NHEAD * SEQ * HDIM];
__device__ float g_v[BATCH * NHEAD * SEQ * HDIM];
__device__ float g_ao[MROWS * INNER];               // attention out, [B,N,H*D]

// ---------------------------------------------------------------------------
// TF32 mma helpers
// ---------------------------------------------------------------------------
__device__ __forceinline__ unsigned f2tf(float f) {
    unsigned u;
    asm("cvt.rna.tf32.f32 %0, %1;" : "=r"(u) : "f"(f));
    return u;
}

__device__ __forceinline__ void mma8(float* c, const unsigned* a, const unsigned* b) {
    asm volatile(
        "mma.sync.aligned.m16n8k8.row.col.f32.tf32.tf32.f32 "
        "{%0,%1,%2,%3}, {%4,%5,%6,%7}, {%8,%9}, {%0,%1,%2,%3};"
        : "+f"(c[0]), "+f"(c[1]), "+f"(c[2]), "+f"(c[3])
        : "r"(a[0]), "r"(a[1]), "r"(a[2]), "r"(a[3]), "r"(b[0]), "r"(b[1]));
}

// ---------------------------------------------------------------------------
// Shared GEMM mainloop: C[128x128] tile, BK=32, 256 threads (8 warps 2x4),
// warp tile 64x32 (4 m16 x 4 n8). tf32-rounded at smem store.
// As: [128][AST] m-major (AST=36, ≡4 mod 32 -> a-frag conflict-free)
// Bs: [32][BST]  k-major (BST=136, ≡8 mod 32 -> b-frag conflict-free)
// ---------------------------------------------------------------------------
#define AST 36
#define BST 136

template<int KDIM>
__device__ __forceinline__ void gemm_mainloop(
    const float* __restrict__ A, int lda,
    const float* __restrict__ B, int ldb,
    float acc[4][4][4], float* As, float* Bs, int row0, int col0)
{
    const int tid  = threadIdx.x;
    const int lane = tid & 31;
    const int warp = tid >> 5;
    const int wm   = (warp >> 2) * 64;
    const int wn   = (warp & 3) * 32;
    const int g    = lane >> 2, t = lane & 3;

    for (int kt = 0; kt < KDIM; kt += 32) {
        #pragma unroll
        for (int i = 0; i < 4; i++) {           // A tile 128x32
            int f = tid + i * 256;
            int r = f >> 3, c = (f & 7) * 4;
            float4 v = *(const float4*)&A[(size_t)(row0 + r) * lda + kt + c];
            unsigned* dst = (unsigned*)&As[r * AST + c];
            dst[0] = f2tf(v.x); dst[1] = f2tf(v.y);
            dst[2] = f2tf(v.z); dst[3] = f2tf(v.w);
        }
        #pragma unroll
        for (int i = 0; i < 4; i++) {           // B tile 32x128
            int f = tid + i * 256;
            int r = f >> 5, c = (f & 31) * 4;
            float4 v = *(const float4*)&B[(size_t)(kt + r) * ldb + col0 + c];
            unsigned* dst = (unsigned*)&Bs[r * BST + c];
            dst[0] = f2tf(v.x); dst[1] = f2tf(v.y);
            dst[2] = f2tf(v.z); dst[3] = f2tf(v.w);
        }
        __syncthreads();

        const unsigned* Au = (const unsigned*)As;
        const unsigned* Bu = (const unsigned*)Bs;
        #pragma unroll
        for (int ks = 0; ks < 4; ks++) {
            unsigned a[4][4], b[4][2];
            #pragma unroll
            for (int mt = 0; mt < 4; mt++) {
                int m = wm + mt * 16;
                a[mt][0] = Au[(m + g) * AST + ks * 8 + t];
                a[mt][1] = Au[(m + g + 8) * AST + ks * 8 + t];
                a[mt][2] = Au[(m + g) * AST + ks * 8 + t + 4];
                a[mt][3] = Au[(m + g + 8) * AST + ks * 8 + t + 4];
            }
            #pragma unroll
            for (int nt = 0; nt < 4; nt++) {
                int n = wn + nt * 8 + g;
                b[nt][0] = Bu[(ks * 8 + t) * BST + n];
                b[nt][1] = Bu[(ks * 8 + t + 4) * BST + n];
            }
            #pragma unroll
            for (int mt = 0; mt < 4; mt++)
                #pragma unroll
                for (int nt = 0; nt < 4; nt++)
                    mma8(acc[mt][nt], a[mt], b[nt]);
        }
        __syncthreads();
    }
}

// ---------------------------------------------------------------------------
// Kernel 1: QKV projection, scatter to Q/K/V [B,H,N,D]; Q pre-scaled.
// ---------------------------------------------------------------------------
__global__ __launch_bounds__(256) void qkv_gemm_kernel(
    const float* __restrict__ A,     // [8192, 1024]
    const float* __restrict__ W,     // [1024, 1536]
    const float* __restrict__ bias)  // [1536]
{
    __shared__ float As[128 * AST];
    __shared__ float Bs[32 * BST];
    const int tid  = threadIdx.x;
    const int lane = tid & 31, warp = tid >> 5;
    const int wm = (warp >> 2) * 64, wn = (warp & 3) * 32;
    const int g = lane >> 2, t = lane & 3;
    const int row0 = blockIdx.y * 128;
    const int col0 = blockIdx.x * 128;

    float acc[4][4][4];
    #pragma unroll
    for (int mt = 0; mt < 4; mt++)
        #pragma unroll
        for (int nt = 0; nt < 4; nt++)
            #pragma unroll
            for (int r = 0; r < 4; r++) acc[mt][nt][r] = 0.f;

    gemm_mainloop<EMBED>(A, EMBED, W, QKVN, acc, As, Bs, row0, col0);

    #pragma unroll
    for (int mt = 0; mt < 4; mt++) {
        #pragma unroll
        for (int half = 0; half < 2; half++) {
            int m  = row0 + wm + mt * 16 + g + half * 8;
            int bb = m >> 12;
            int n  = m & (SEQ - 1);
            #pragma unroll
            for (int nt = 0; nt < 4; nt++) {
                #pragma unroll
                for (int jj = 0; jj < 2; jj++) {
                    int o = col0 + wn + nt * 8 + t * 2 + jj;
                    float val = acc[mt][nt][half * 2 + jj] + bias[o];
                    int part  = o >> 9;
                    int inner = o & 511;
                    int h = inner >> 6, d = inner & 63;
                    size_t idx = (((size_t)(bb * NHEAD + h)) * SEQ + n) * HDIM + d;
                    if (part == 0)      g_q[idx] = val * 0.125f;
                    else if (part == 1) g_k[idx] = val;
                    else                g_v[idx] = val;
                }
            }
        }
    }
}

// ---------------------------------------------------------------------------
// Kernel 2: flash attention with tf32 mma. BQ=64, BKV=64, 128 threads.
// Warp w owns q rows [w*16, w*16+16). Fragments:
//   S = Q K^T : A from Qs (stride 68 ≡4), B from Ks (stride 68 ≡4 works: 4g+t)
//   O += P V  : A from Ps (stride 68),    B from Vs (stride 72 ≡8: 8t+g)
// ---------------------------------------------------------------------------
#define QST 68
#define KST 68
#define VST 72
#define PST 68
#define ATT_SMEM_BYTES ((64 * QST + 64 * KST + 64 * VST + 64 * PST) * 4)  // 70656

__global__ __launch_bounds__(128) void attn_kernel()
{
    extern __shared__ float sm[];
    float* Qs = sm;
    float* Ks = Qs + 64 * QST;
    float* Vs = Ks + 64 * KST;
    float* Ps = Vs + 64 * VST;

    const int tid  = threadIdx.x;
    const int lane = tid & 31, warp = tid >> 5;
    const int g = lane >> 2, t = lane & 3;
    const int bh = blockIdx.y;
    const int q0 = blockIdx.x * 64;
    const int w16 = warp * 16;

    const float* Qg = g_q + ((size_t)bh * SEQ + q0) * HDIM;
    const float* Kg = g_k + (size_t)bh * SEQ * HDIM;
    const float* Vg = g_v + (size_t)bh * SEQ * HDIM;

    // Load + round Q (64x64)
    #pragma unroll
    for (int i = 0; i < 8; i++) {
        int f = tid + i * 128;
        int r = f >> 4, c = (f & 15) * 4;
        float4 v = *(const float4*)&Qg[(size_t)r * HDIM + c];
        unsigned* dst = (unsigned*)&Qs[r * QST + c];
        dst[0] = f2tf(v.x); dst[1] = f2tf(v.y);
        dst[2] = f2tf(v.z); dst[3] = f2tf(v.w);
    }

    float o[8][4];
    float m_i[2], l_i[2];
    #pragma unroll
    for (int nt = 0; nt < 8; nt++)
        #pragma unroll
        for (int r = 0; r < 4; r++) o[nt][r] = 0.f;
    m_i[0] = m_i[1] = -1e30f;
    l_i[0] = l_i[1] = 0.f;

    const unsigned* Qu = (const unsigned*)Qs;
    const unsigned* Ku = (const unsigned*)Ks;
    const unsigned* Vu = (const unsigned*)Vs;
    const unsigned* Pu = (const unsigned*)Ps;

    for (int kt = 0; kt < SEQ; kt += 64) {
        __syncthreads();   // prior tile fully consumed (also orders Q on iter 0)
        #pragma unroll
        for (int i = 0; i < 8; i++) {
            int f = tid + i * 128;
            int r = f >> 4, c = (f & 15) * 4;
            float4 kv = *(const float4*)&Kg[(size_t)(kt + r) * HDIM + c];
            unsigned* kd = (unsigned*)&Ks[r * KST + c];
            kd[0] = f2tf(kv.x); kd[1] = f2tf(kv.y);
            kd[2] = f2tf(kv.z); kd[3] = f2tf(kv.w);
            float4 vv = *(const float4*)&Vg[(size_t)(kt + r) * HDIM + c];
            unsigned* vd = (unsigned*)&Vs[r * VST + c];
            vd[0] = f2tf(vv.x); vd[1] = f2tf(vv.y);
            vd[2] = f2tf(vv.z); vd[3] = f2tf(vv.w);
        }
        __syncthreads();

        // ---- S = Q K^T : 16 x 64 per warp ----
        float s[8][4];
        #pragma unroll
        for (int nt = 0; nt < 8; nt++)
            #pragma unroll
            for (int r = 0; r < 4; r++) s[nt][r] = 0.f;

        #pragma unroll
        for (int ks = 0; ks < 8; ks++) {
            unsigned a[4];
            a[0] = Qu[(w16 + g) * QST + ks * 8 + t];
            a[1] = Qu[(w16 + g + 8) * QST + ks * 8 + t];
            a[2] = Qu[(w16 + g) * QST + ks * 8 + t + 4];
            a[3] = Qu[(w16 + g + 8) * QST + ks * 8 + t + 4];
            #pragma unroll
            for (int nt = 0; nt < 8; nt++) {
                unsigned b[2];
                b[0] = Ku[(nt * 8 + g) * KST + ks * 8 + t];
                b[1] = Ku[(nt * 8 + g) * KST + ks * 8 + t + 4];
                mma8(s[nt], a, b);
            }
        }

        // ---- online softmax on C-fragment layout ----
        __syncwarp();      // prior PV reads of Ps done before overwrite
        #pragma unroll
        for (int half = 0; half < 2; half++) {
            float mx = -1e30f;
            #pragma unroll
            for (int nt = 0; nt < 8; nt++)
                mx = fmaxf(mx, fmaxf(s[nt][half * 2], s[nt][half * 2 + 1]));
            mx = fmaxf(mx, __shfl_xor_sync(0xffffffffu, mx, 1));
            mx = fmaxf(mx, __shfl_xor_sync(0xffffffffu, mx, 2));
            float mn   = fmaxf(m_i[half], mx);
            float corr = __expf(m_i[half] - mn);
            m_i[half] = mn;
            float sum = 0.f;
            #pragma unroll
            for (int nt = 0; nt < 8; nt++) {
                float p0 = __expf(s[nt][half * 2]     - mn);
                float p1 = __expf(s[nt][half * 2 + 1] - mn);
                sum += p0 + p1;
                unsigned* pd = (unsigned*)&Ps[(w16 + g + half * 8) * PST + nt * 8 + t * 2];
                pd[0] = f2tf(p0); pd[1] = f2tf(p1);
                o[nt][half * 2]     *= corr;
                o[nt][half * 2 + 1] *= corr;
            }
            sum += __shfl_xor_sync(0xffffffffu, sum, 1);
            sum += __shfl_xor_sync(0xffffffffu, sum, 2);
            l_i[half] = l_i[half] * corr + sum;
        }
        __syncwarp();      // P visible to whole warp before PV loads

        // ---- O += P V ----
        #pragma unroll
        for (int ks = 0; ks < 8; ks++) {
            unsigned a[4];
            a[0] = Pu[(w16 + g) * PST + ks * 8 + t];
            a[1] = Pu[(w16 + g + 8) * PST + ks * 8 + t];
            a[2] = Pu[(w16 + g) * PST + ks * 8 + t + 4];
            a[3] = Pu[(w16 + g + 8) * PST + ks * 8 + t + 4];
            #pragma unroll
            for (int nt = 0; nt < 8; nt++) {
                unsigned b[2];
                b[0] = Vu[(ks * 8 + t) * VST + nt * 8 + g];
                b[1] = Vu[(ks * 8 + t + 4) * VST + nt * 8 + g];
                mma8(o[nt], a, b);
            }
        }
    }

    // finalize + write [B,N,H*D]
    const int bb = bh >> 3, h = bh & 7;
    #pragma unroll
    for (int half = 0; half < 2; half++) {
        float inv = 1.0f / l_i[half];
        int n = q0 + w16 + g + half * 8;
        float* dst = g_ao + ((size_t)(bb * SEQ + n)) * INNER + h * HDIM;
        #pragma unroll
        for (int nt = 0; nt < 8; nt++) {
            float2 v2;
            v2.x = o[nt][half * 2]     * inv;
            v2.y = o[nt][half * 2 + 1] * inv;
            *(float2*)&dst[nt * 8 + t * 2] = v2;
        }
    }
}

// ---------------------------------------------------------------------------
// Kernel 3: output projection  out = AO @ Wproj + b
// ---------------------------------------------------------------------------
__global__ __launch_bounds__(256) void proj_gemm_kernel(
    const float* __restrict__ W,     // [512, 1024]
    const float* __restrict__ bias,  // [1024]
    float* __restrict__ out)         // [8192, 1024]
{
    __shared__ float As[128 * AST];
    __shared__ float Bs[32 * BST];
    const int tid  = threadIdx.x;
    const int lane = tid & 31, warp = tid >> 5;
    const int wm = (warp >> 2) * 64, wn = (warp & 3) * 32;
    const int g = lane >> 2, t = lane & 3;
    const int row0 = blockIdx.y * 128;
    const int col0 = blockIdx.x * 128;

    float acc[4][4][4];
    #pragma unroll
    for (int mt = 0; mt < 4; mt++)
        #pragma unroll
        for (int nt = 0; nt < 4; nt++)
            #pragma unroll
            for (int r = 0; r < 4; r++) acc[mt][nt][r] = 0.f;

    gemm_mainloop<INNER>(g_ao, INNER, W, EMBED, acc, As, Bs, row0, col0);

    #pragma unroll
    for (int mt = 0; mt < 4; mt++) {
        #pragma unroll
        for (int half = 0; half < 2; half++) {
            int m = row0 + wm + mt * 16 + g + half * 8;
            #pragma unroll
            for (int nt = 0; nt < 4; nt++) {
                int n = col0 + wn + nt * 8 + t * 2;
                float2 v2;
                v2.x = acc[mt][nt][half * 2]     + bias[n];
                v2.y = acc[mt][nt][half * 2 + 1] + bias[n + 1];
                *(float2*)&out[(size_t)m * EMBED + n] = v2;
            }
        }
    }
}

// ---------------------------------------------------------------------------
extern "C" void kernel_launch(void* const* d_in, const int* in_sizes, int n_in,
                              void* d_out, int out_size)
{
    const float* X     = (const float*)d_in[0];
    const float* Wqkv  = (const float*)d_in[1];
    const float* Bqkv  = (const float*)d_in[2];
    const float* Wproj = (const float*)d_in[3];
    const float* Bproj = (const float*)d_in[4];
    float* out = (float*)d_out;

    cudaFuncSetAttribute(attn_kernel,
                         cudaFuncAttributeMaxDynamicSharedMemorySize,
                         ATT_SMEM_BYTES);

    qkv_gemm_kernel<<<dim3(QKVN / 128, MROWS / 128), 256>>>(X, Wqkv, Bqkv);
    attn_kernel<<<dim3(SEQ / 64, BATCH * NHEAD), 128, ATT_SMEM_BYTES>>>();
    proj_gemm_kernel<<<dim3(EMBED / 128, MROWS / 128), 256>>>(Wproj, Bproj, out);
}

// round 8
// speedup vs baseline: 1.0006x; 1.0002x over previous
#include <cuda_runtime.h>
#include <math.h>

#define EMBED 1024
#define QKVN  1536
#define INNER 512
#define NHEAD 8
#define HDIM  64
#define BATCH 2
#define SEQ   4096
#define MROWS (BATCH * SEQ)   // 8192

// Scratch (allocation-free rule: __device__ globals)
__device__ float g_q[BATCH * NHEAD * SEQ * HDIM];   // [B,H,N,D], pre-scaled by 0.125
__device__ float g_k[BATCH * NHEAD * SEQ * HDIM];
__device__ float g_v[BATCH * NHEAD * SEQ * HDIM];
__device__ float g_ao[MROWS * INNER];               // attention out, [B,N,H*D]

// ---------------------------------------------------------------------------
// TF32 mma helpers
// ---------------------------------------------------------------------------
__device__ __forceinline__ unsigned f2tf(float f) {
    unsigned u;
    asm("cvt.rna.tf32.f32 %0, %1;" : "=r"(u) : "f"(f));
    return u;
}

__device__ __forceinline__ void mma8(float* c, const unsigned* a, const unsigned* b) {
    asm volatile(
        "mma.sync.aligned.m16n8k8.row.col.f32.tf32.tf32.f32 "
        "{%0,%1,%2,%3}, {%4,%5,%6,%7}, {%8,%9}, {%0,%1,%2,%3};"
        : "+f"(c[0]), "+f"(c[1]), "+f"(c[2]), "+f"(c[3])
        : "r"(a[0]), "r"(a[1]), "r"(a[2]), "r"(a[3]), "r"(b[0]), "r"(b[1]));
}

// ---------------------------------------------------------------------------
// Shared GEMM mainloop: C[128x128] tile, BK=32, 256 threads (8 warps 2x4),
// warp tile 64x32 (4 m16 x 4 n8). tf32-rounded at smem store.
// As: [128][AST] m-major (AST=36, ≡4 mod 32 -> a-frag conflict-free)
// Bs: [32][BST]  k-major (BST=136, ≡8 mod 32 -> b-frag conflict-free)
// ---------------------------------------------------------------------------
#define AST 36
#define BST 136

template<int KDIM>
__device__ __forceinline__ void gemm_mainloop(
    const float* __restrict__ A, int lda,
    const float* __restrict__ B, int ldb,
    float acc[4][4][4], float* As, float* Bs, int row0, int col0)
{
    const int tid  = threadIdx.x;
    const int lane = tid & 31;
    const int warp = tid >> 5;
    const int wm   = (warp >> 2) * 64;
    const int wn   = (warp & 3) * 32;
    const int g    = lane >> 2, t = lane & 3;

    for (int kt = 0; kt < KDIM; kt += 32) {
        #pragma unroll
        for (int i = 0; i < 4; i++) {           // A tile 128x32
            int f = tid + i * 256;
            int r = f >> 3, c = (f & 7) * 4;
            float4 v = *(const float4*)&A[(size_t)(row0 + r) * lda + kt + c];
            unsigned* dst = (unsigned*)&As[r * AST + c];
            dst[0] = f2tf(v.x); dst[1] = f2tf(v.y);
            dst[2] = f2tf(v.z); dst[3] = f2tf(v.w);
        }
        #pragma unroll
        for (int i = 0; i < 4; i++) {           // B tile 32x128
            int f = tid + i * 256;
            int r = f >> 5, c = (f & 31) * 4;
            float4 v = *(const float4*)&B[(size_t)(kt + r) * ldb + col0 + c];
            unsigned* dst = (unsigned*)&Bs[r * BST + c];
            dst[0] = f2tf(v.x); dst[1] = f2tf(v.y);
            dst[2] = f2tf(v.z); dst[3] = f2tf(v.w);
        }
        __syncthreads();

        const unsigned* Au = (const unsigned*)As;
        const unsigned* Bu = (const unsigned*)Bs;
        #pragma unroll
        for (int ks = 0; ks < 4; ks++) {
            unsigned a[4][4], b[4][2];
            #pragma unroll
            for (int mt = 0; mt < 4; mt++) {
                int m = wm + mt * 16;
                a[mt][0] = Au[(m + g) * AST + ks * 8 + t];
                a[mt][1] = Au[(m + g + 8) * AST + ks * 8 + t];
                a[mt][2] = Au[(m + g) * AST + ks * 8 + t + 4];
                a[mt][3] = Au[(m + g + 8) * AST + ks * 8 + t + 4];
            }
            #pragma unroll
            for (int nt = 0; nt < 4; nt++) {
                int n = wn + nt * 8 + g;
                b[nt][0] = Bu[(ks * 8 + t) * BST + n];
                b[nt][1] = Bu[(ks * 8 + t + 4) * BST + n];
            }
            #pragma unroll
            for (int mt = 0; mt < 4; mt++)
                #pragma unroll
                for (int nt = 0; nt < 4; nt++)
                    mma8(acc[mt][nt], a[mt], b[nt]);
        }
        __syncthreads();
    }
}

// ---------------------------------------------------------------------------
// Kernel 1: QKV projection, scatter to Q/K/V [B,H,N,D]; Q pre-scaled.
// ---------------------------------------------------------------------------
__global__ __launch_bounds__(256) void qkv_gemm_kernel(
    const float* __restrict__ A,     // [8192, 1024]
    const float* __restrict__ W,     // [1024, 1536]
    const float* __restrict__ bias)  // [1536]
{
    __shared__ float As[128 * AST];
    __shared__ float Bs[32 * BST];
    const int tid  = threadIdx.x;
    const int lane = tid & 31, warp = tid >> 5;
    const int wm = (warp >> 2) * 64, wn = (warp & 3) * 32;
    const int g = lane >> 2, t = lane & 3;
    const int row0 = blockIdx.y * 128;
    const int col0 = blockIdx.x * 128;

    float acc[4][4][4];
    #pragma unroll
    for (int mt = 0; mt < 4; mt++)
        #pragma unroll
        for (int nt = 0; nt < 4; nt++)
            #pragma unroll
            for (int r = 0; r < 4; r++) acc[mt][nt][r] = 0.f;

    gemm_mainloop<EMBED>(A, EMBED, W, QKVN, acc, As, Bs, row0, col0);

    #pragma unroll
    for (int mt = 0; mt < 4; mt++) {
        #pragma unroll
        for (int half = 0; half < 2; half++) {
            int m  = row0 + wm + mt * 16 + g + half * 8;
            int bb = m >> 12;
            int n  = m & (SEQ - 1);
            #pragma unroll
            for (int nt = 0; nt < 4; nt++) {
                #pragma unroll
                for (int jj = 0; jj < 2; jj++) {
                    int o = col0 + wn + nt * 8 + t * 2 + jj;
                    float val = acc[mt][nt][half * 2 + jj] + bias[o];
                    int part  = o >> 9;
                    int inner = o & 511;
                    int h = inner >> 6, d = inner & 63;
                    size_t idx = (((size_t)(bb * NHEAD + h)) * SEQ + n) * HDIM + d;
                    if (part == 0)      g_q[idx] = val * 0.125f;
                    else if (part == 1) g_k[idx] = val;
                    else                g_v[idx] = val;
                }
            }
        }
    }
}

// ---------------------------------------------------------------------------
// Kernel 2: flash attention with tf32 mma. BQ=64, BKV=64, 128 threads.
// Warp w owns q rows [w*16, w*16+16). Fragments:
//   S = Q K^T : A from Qs (stride 68 ≡4), B from Ks (stride 68 ≡4 works: 4g+t)
//   O += P V  : A from Ps (stride 68),    B from Vs (stride 72 ≡8: 8t+g)
// ---------------------------------------------------------------------------
#define QST 68
#define KST 68
#define VST 72
#define PST 68
#define ATT_SMEM_BYTES ((64 * QST + 64 * KST + 64 * VST + 64 * PST) * 4)  // 70656

__global__ __launch_bounds__(128) void attn_kernel()
{
    extern __shared__ float sm[];
    float* Qs = sm;
    float* Ks = Qs + 64 * QST;
    float* Vs = Ks + 64 * KST;
    float* Ps = Vs + 64 * VST;

    const int tid  = threadIdx.x;
    const int lane = tid & 31, warp = tid >> 5;
    const int g = lane >> 2, t = lane & 3;
    const int bh = blockIdx.y;
    const int q0 = blockIdx.x * 64;
    const int w16 = warp * 16;

    const float* Qg = g_q + ((size_t)bh * SEQ + q0) * HDIM;
    const float* Kg = g_k + (size_t)bh * SEQ * HDIM;
    const float* Vg = g_v + (size_t)bh * SEQ * HDIM;

    // Load + round Q (64x64)
    #pragma unroll
    for (int i = 0; i < 8; i++) {
        int f = tid + i * 128;
        int r = f >> 4, c = (f & 15) * 4;
        float4 v = *(const float4*)&Qg[(size_t)r * HDIM + c];
        unsigned* dst = (unsigned*)&Qs[r * QST + c];
        dst[0] = f2tf(v.x); dst[1] = f2tf(v.y);
        dst[2] = f2tf(v.z); dst[3] = f2tf(v.w);
    }

    float o[8][4];
    float m_i[2], l_i[2];
    #pragma unroll
    for (int nt = 0; nt < 8; nt++)
        #pragma unroll
        for (int r = 0; r < 4; r++) o[nt][r] = 0.f;
    m_i[0] = m_i[1] = -1e30f;
    l_i[0] = l_i[1] = 0.f;

    const unsigned* Qu = (const unsigned*)Qs;
    const unsigned* Ku = (const unsigned*)Ks;
    const unsigned* Vu = (const unsigned*)Vs;
    const unsigned* Pu = (const unsigned*)Ps;

    for (int kt = 0; kt < SEQ; kt += 64) {
        __syncthreads();   // prior tile fully consumed (also orders Q on iter 0)
        #pragma unroll
        for (int i = 0; i < 8; i++) {
            int f = tid + i * 128;
            int r = f >> 4, c = (f & 15) * 4;
            float4 kv = *(const float4*)&Kg[(size_t)(kt + r) * HDIM + c];
            unsigned* kd = (unsigned*)&Ks[r * KST + c];
            kd[0] = f2tf(kv.x); kd[1] = f2tf(kv.y);
            kd[2] = f2tf(kv.z); kd[3] = f2tf(kv.w);
            float4 vv = *(const float4*)&Vg[(size_t)(kt + r) * HDIM + c];
            unsigned* vd = (unsigned*)&Vs[r * VST + c];
            vd[0] = f2tf(vv.x); vd[1] = f2tf(vv.y);
            vd[2] = f2tf(vv.z); vd[3] = f2tf(vv.w);
        }
        __syncthreads();

        // ---- S = Q K^T : 16 x 64 per warp ----
        float s[8][4];
        #pragma unroll
        for (int nt = 0; nt < 8; nt++)
            #pragma unroll
            for (int r = 0; r < 4; r++) s[nt][r] = 0.f;

        #pragma unroll
        for (int ks = 0; ks < 8; ks++) {
            unsigned a[4];
            a[0] = Qu[(w16 + g) * QST + ks * 8 + t];
            a[1] = Qu[(w16 + g + 8) * QST + ks * 8 + t];
            a[2] = Qu[(w16 + g) * QST + ks * 8 + t + 4];
            a[3] = Qu[(w16 + g + 8) * QST + ks * 8 + t + 4];
            #pragma unroll
            for (int nt = 0; nt < 8; nt++) {
                unsigned b[2];
                b[0] = Ku[(nt * 8 + g) * KST + ks * 8 + t];
                b[1] = Ku[(nt * 8 + g) * KST + ks * 8 + t + 4];
                mma8(s[nt], a, b);
            }
        }

        // ---- online softmax on C-fragment layout ----
        __syncwarp();      // prior PV reads of Ps done before overwrite
        #pragma unroll
        for (int half = 0; half < 2; half++) {
            float mx = -1e30f;
            #pragma unroll
            for (int nt = 0; nt < 8; nt++)
                mx = fmaxf(mx, fmaxf(s[nt][half * 2], s[nt][half * 2 + 1]));
            mx = fmaxf(mx, __shfl_xor_sync(0xffffffffu, mx, 1));
            mx = fmaxf(mx, __shfl_xor_sync(0xffffffffu, mx, 2));
            float mn   = fmaxf(m_i[half], mx);
            float corr = __expf(m_i[half] - mn);
            m_i[half] = mn;
            float sum = 0.f;
            #pragma unroll
            for (int nt = 0; nt < 8; nt++) {
                float p0 = __expf(s[nt][half * 2]     - mn);
                float p1 = __expf(s[nt][half * 2 + 1] - mn);
                sum += p0 + p1;
                unsigned* pd = (unsigned*)&Ps[(w16 + g + half * 8) * PST + nt * 8 + t * 2];
                pd[0] = f2tf(p0); pd[1] = f2tf(p1);
                o[nt][half * 2]     *= corr;
                o[nt][half * 2 + 1] *= corr;
            }
            sum += __shfl_xor_sync(0xffffffffu, sum, 1);
            sum += __shfl_xor_sync(0xffffffffu, sum, 2);
            l_i[half] = l_i[half] * corr + sum;
        }
        __syncwarp();      // P visible to whole warp before PV loads

        // ---- O += P V ----
        #pragma unroll
        for (int ks = 0; ks < 8; ks++) {
            unsigned a[4];
            a[0] = Pu[(w16 + g) * PST + ks * 8 + t];
            a[1] = Pu[(w16 + g + 8) * PST + ks * 8 + t];
            a[2] = Pu[(w16 + g) * PST + ks * 8 + t + 4];
            a[3] = Pu[(w16 + g + 8) * PST + ks * 8 + t + 4];
            #pragma unroll
            for (int nt = 0; nt < 8; nt++) {
                unsigned b[2];
                b[0] = Vu[(ks * 8 + t) * VST + nt * 8 + g];
                b[1] = Vu[(ks * 8 + t + 4) * VST + nt * 8 + g];
                mma8(o[nt], a, b);
            }
        }
    }

    // finalize + write [B,N,H*D]
    const int bb = bh >> 3, h = bh & 7;
    #pragma unroll
    for (int half = 0; half < 2; half++) {
        float inv = 1.0f / l_i[half];
        int n = q0 + w16 + g + half * 8;
        float* dst = g_ao + ((size_t)(bb * SEQ + n)) * INNER + h * HDIM;
        #pragma unroll
        for (int nt = 0; nt < 8; nt++) {
            float2 v2;
            v2.x = o[nt][half * 2]     * inv;
            v2.y = o[nt][half * 2 + 1] * inv;
            *(float2*)&dst[nt * 8 + t * 2] = v2;
        }
    }
}

// ---------------------------------------------------------------------------
// Kernel 3: output projection  out = AO @ Wproj + b
// ---------------------------------------------------------------------------
__global__ __launch_bounds__(256) void proj_gemm_kernel(
    const float* __restrict__ W,     // [512, 1024]
    const float* __restrict__ bias,  // [1024]
    float* __restrict__ out)         // [8192, 1024]
{
    __shared__ float As[128 * AST];
    __shared__ float Bs[32 * BST];
    const int tid  = threadIdx.x;
    const int lane = tid & 31, warp = tid >> 5;
    const int wm = (warp >> 2) * 64, wn = (warp & 3) * 32;
    const int g = lane >> 2, t = lane & 3;
    const int row0 = blockIdx.y * 128;
    const int col0 = blockIdx.x * 128;

    float acc[4][4][4];
    #pragma unroll
    for (int mt = 0; mt < 4; mt++)
        #pragma unroll
        for (int nt = 0; nt < 4; nt++)
            #pragma unroll
            for (int r = 0; r < 4; r++) acc[mt][nt][r] = 0.f;

    gemm_mainloop<INNER>(g_ao, INNER, W, EMBED, acc, As, Bs, row0, col0);

    #pragma unroll
    for (int mt = 0; mt < 4; mt++) {
        #pragma unroll
        for (int half = 0; half < 2; half++) {
            int m = row0 + wm + mt * 16 + g + half * 8;
            #pragma unroll
            for (int nt = 0; nt < 4; nt++) {
                int n = col0 + wn + nt * 8 + t * 2;
                float2 v2;
                v2.x = acc[mt][nt][half * 2]     + bias[n];
                v2.y = acc[mt][nt][half * 2 + 1] + bias[n + 1];
                *(float2*)&out[(size_t)m * EMBED + n] = v2;
            }
        }
    }
}

// ---------------------------------------------------------------------------
extern "C" void kernel_launch(void* const* d_in, const int* in_sizes, int n_in,
                              void* d_out, int out_size)
{
    const float* X     = (const float*)d_in[0];
    const float* Wqkv  = (const float*)d_in[1];
    const float* Bqkv  = (const float*)d_in[2];
    const float* Wproj = (const float*)d_in[3];
    const float* Bproj = (const float*)d_in[4];
    float* out = (float*)d_out;

    cudaFuncSetAttribute(attn_kernel,
                         cudaFuncAttributeMaxDynamicSharedMemorySize,
                         ATT_SMEM_BYTES);

    qkv_gemm_kernel<<<dim3(QKVN / 128, MROWS / 128), 256>>>(X, Wqkv, Bqkv);
    attn_kernel<<<dim3(SEQ / 64, BATCH * NHEAD), 128, ATT_SMEM_BYTES>>>();
    proj_gemm_kernel<<<dim3(EMBED / 128, MROWS / 128), 256>>>(Wproj, Bproj, out);
}